// round 1
// baseline (speedup 1.0000x reference)
#include <cuda_runtime.h>
#include <cuda_bf16.h>

// Problem constants
#define NW      16384   // words
#define LCH     16      // chars per word
#define CEMB    64      // char emb dim
#define CO      256     // conv out channels
#define DEMB    300     // word emb dim
#define OUTW    556     // 256 + 300
#define OCHUNK  128     // channels per block (blockIdx.y in {0,1})

// Precomputed conv tables: M[k][c][o] = sum_e char_emb[c,e] * conv_w[o,e,k]
// 3 * 128 * 256 floats = 384 KB
__device__ float g_M[3 * 128 * 256];

// ---------------------------------------------------------------------------
// Kernel 1: build tables. grid = 256 (o), block = 128 (c).
// ---------------------------------------------------------------------------
__global__ void build_tables_kernel(const float* __restrict__ ce_w,
                                    const float* __restrict__ conv_w) {
    __shared__ float se[64 * 128];   // se[e*128 + c], conflict-free reads
    const int o = blockIdx.x;
    const int c = threadIdx.x;

    // coalesced global read of char_emb_w [128, 64]
    for (int i = threadIdx.x; i < 128 * 64; i += 128) {
        int cc = i >> 6;
        int e  = i & 63;
        se[e * 128 + cc] = ce_w[i];
    }
    __syncthreads();

    const float* wp = conv_w + o * (CEMB * 3);   // conv_w[o][e][k], contiguous 192
    float a0 = 0.f, a1 = 0.f, a2 = 0.f;
#pragma unroll
    for (int e = 0; e < CEMB; ++e) {
        float w0 = wp[e * 3 + 0];   // uniform across lanes (broadcast)
        float w1 = wp[e * 3 + 1];
        float w2 = wp[e * 3 + 2];
        float s  = se[e * 128 + c];
        a0 = fmaf(s, w0, a0);
        a1 = fmaf(s, w1, a1);
        a2 = fmaf(s, w2, a2);
    }
    g_M[(0 * 128 + c) * 256 + o] = a0;
    g_M[(1 * 128 + c) * 256 + o] = a1;
    g_M[(2 * 128 + c) * 256 + o] = a2;
}

// ---------------------------------------------------------------------------
// Kernel 2: main. grid = (74, 2), block = 512 threads, 192 KB dyn smem.
// Each warp handles one word at a time: lane covers 4 channels (float4).
// blockIdx.y selects the 128-channel half. y==0 half also copies word emb.
// ---------------------------------------------------------------------------
__device__ __forceinline__ float4 f4add(float4 a, float4 b) {
    return make_float4(a.x + b.x, a.y + b.y, a.z + b.z, a.w + b.w);
}
__device__ __forceinline__ float4 f4max(float4 a, float4 b) {
    return make_float4(fmaxf(a.x, b.x), fmaxf(a.y, b.y),
                       fmaxf(a.z, b.z), fmaxf(a.w, b.w));
}

extern "C" __global__ void __launch_bounds__(512, 1)
wordchar_main_kernel(const int* __restrict__ X,
                     const int* __restrict__ Xword,
                     const float* __restrict__ conv_b,
                     const float* __restrict__ wemb,
                     float* __restrict__ out) {
    extern __shared__ float Ms[];            // [3][128][OCHUNK]
    float4* Ms4 = reinterpret_cast<float4*>(Ms);

    const int half   = blockIdx.y;
    const int o_base = half * OCHUNK;

    // stage tables: 3*128*OCHUNK floats = 3*128*32 float4
    {
        const float4* Mg4 = reinterpret_cast<const float4*>(g_M);
        const int nf4 = 3 * 128 * (OCHUNK / 4);          // 12288
        for (int i4 = threadIdx.x; i4 < nf4; i4 += blockDim.x) {
            int k   = i4 >> 12;                          // / (128*32)
            int rem = i4 & 4095;
            int c   = rem >> 5;                          // / 32
            int oc4 = rem & 31;
            Ms4[i4] = Mg4[(k * 128 + c) * 64 + (o_base >> 2) + oc4];
        }
    }
    __syncthreads();

    const int warp  = threadIdx.x >> 5;
    const int lane  = threadIdx.x & 31;
    const int gwarp  = blockIdx.x * (blockDim.x >> 5) + warp;
    const int nwarps = gridDim.x * (blockDim.x >> 5);

    const float4 b4 = *reinterpret_cast<const float4*>(conv_b + o_base + lane * 4);

    for (int w = gwarp; w < NW; w += nwarps) {
        // load 16 chars (uniform across warp -> broadcast)
        const int4* xr = reinterpret_cast<const int4*>(X + w * LCH);
        int4 x0 = xr[0], x1 = xr[1], x2 = xr[2], x3 = xr[3];
        int xs[16];
        xs[0]=x0.x; xs[1]=x0.y; xs[2]=x0.z; xs[3]=x0.w;
        xs[4]=x1.x; xs[5]=x1.y; xs[6]=x1.z; xs[7]=x1.w;
        xs[8]=x2.x; xs[9]=x2.y; xs[10]=x2.z; xs[11]=x2.w;
        xs[12]=x3.x; xs[13]=x3.y; xs[14]=x3.z; xs[15]=x3.w;

        // sliding-window conv + max over t in [0, 18)
        // y[t] = M0[x[t-2]] + M1[x[t-1]] + M2[x[t]]  (terms dropped OOB)
        float4 maxs, pp0, p0, p1;
#pragma unroll
        for (int t = 0; t < 16; ++t) {
            int c = xs[t];
            float4 m0 = Ms4[(0 * 128 + c) * 32 + lane];
            float4 m1 = Ms4[(1 * 128 + c) * 32 + lane];
            float4 m2 = Ms4[(2 * 128 + c) * 32 + lane];
            float4 y = m2;
            if (t >= 1) y = f4add(y, p1);
            if (t >= 2) y = f4add(y, pp0);
            maxs = (t == 0) ? y : f4max(maxs, y);
            pp0 = p0;
            p0  = m0;
            p1  = m1;
        }
        // t = 16: y = M0[x[14]] + M1[x[15]]
        maxs = f4max(maxs, f4add(p1, pp0));
        // t = 17: y = M0[x[15]]
        maxs = f4max(maxs, p0);

        // relu(max + bias)
        float4 r;
        r.x = fmaxf(maxs.x + b4.x, 0.f);
        r.y = fmaxf(maxs.y + b4.y, 0.f);
        r.z = fmaxf(maxs.z + b4.z, 0.f);
        r.w = fmaxf(maxs.w + b4.w, 0.f);
        *reinterpret_cast<float4*>(out + (size_t)w * OUTW + o_base + lane * 4) = r;

        // word embedding copy (only the y==0 half does it)
        if (half == 0) {
            int wi = Xword[w];
            const float4* src = reinterpret_cast<const float4*>(wemb + (size_t)wi * DEMB);
            float4* dst = reinterpret_cast<float4*>(out + (size_t)w * OUTW + CO);
#pragma unroll
            for (int j = lane; j < DEMB / 4; j += 32)   // 75 float4
                dst[j] = src[j];
        }
    }
}

// ---------------------------------------------------------------------------
// Launch
// ---------------------------------------------------------------------------
extern "C" void kernel_launch(void* const* d_in, const int* in_sizes, int n_in,
                              void* d_out, int out_size) {
    const int*   X        = (const int*)  d_in[0];   // [16384,16]
    const int*   X_word   = (const int*)  d_in[1];   // [16384]
    const float* char_emb = (const float*)d_in[2];   // [128,64]
    const float* conv_w   = (const float*)d_in[3];   // [256,64,3]
    const float* conv_b   = (const float*)d_in[4];   // [256]
    const float* word_emb = (const float*)d_in[5];   // [50000,300]
    float*       out      = (float*)d_out;           // [16384,556]

    build_tables_kernel<<<256, 128>>>(char_emb, conv_w);

    const int smem = 3 * 128 * OCHUNK * (int)sizeof(float);   // 196608
    cudaFuncSetAttribute(wordchar_main_kernel,
                         cudaFuncAttributeMaxDynamicSharedMemorySize, smem);
    dim3 grid(74, 2);
    wordchar_main_kernel<<<grid, 512, smem>>>(X, X_word, conv_b, word_emb, out);
}

// round 2
// speedup vs baseline: 1.0329x; 1.0329x over previous
#include <cuda_runtime.h>
#include <cuda_fp16.h>

// Problem constants
#define NW      16384   // words
#define LCH     16      // chars per word
#define CEMB    64      // char emb dim
#define CO      256     // conv out channels
#define DEMB    300     // word emb dim
#define OUTW    556     // 256 + 300
#define OCHUNK  128     // channels per block (blockIdx.y in {0,1})

// Precomputed conv tables (fp16): M[k][c][o] = sum_e char_emb[c,e]*conv_w[o,e,k]
// 3 * 128 * 256 halves = 192 KB
__device__ __half g_Mh[3 * 128 * 256];

// ---------------------------------------------------------------------------
// Kernel 1: build tables. grid = 128 (c), block = 256 (o).
// Writes are coalesced across o (contiguous 512B per (k,c) row).
// ---------------------------------------------------------------------------
__global__ void build_tables_kernel(const float* __restrict__ ce_w,
                                    const float* __restrict__ conv_w) {
    __shared__ float se[CEMB];
    const int c = blockIdx.x;
    const int o = threadIdx.x;

    if (threadIdx.x < CEMB) se[threadIdx.x] = ce_w[c * CEMB + threadIdx.x];
    __syncthreads();

    const float* wp = conv_w + o * (CEMB * 3);   // conv_w[o][e][k], 192 contiguous
    float a0 = 0.f, a1 = 0.f, a2 = 0.f;
#pragma unroll
    for (int e = 0; e < CEMB; ++e) {
        float s = se[e];
        a0 = fmaf(s, wp[e * 3 + 0], a0);
        a1 = fmaf(s, wp[e * 3 + 1], a1);
        a2 = fmaf(s, wp[e * 3 + 2], a2);
    }
    g_Mh[(0 * 128 + c) * 256 + o] = __float2half_rn(a0);
    g_Mh[(1 * 128 + c) * 256 + o] = __float2half_rn(a1);
    g_Mh[(2 * 128 + c) * 256 + o] = __float2half_rn(a2);
}

// ---------------------------------------------------------------------------
// Kernel 2: main. grid = (148, 2), block = 512, 96 KB dyn smem, 2 CTAs/SM.
// Warp handles one word; lane covers 4 channels as 2x half2 (LDS.64).
// blockIdx.y selects the 128-channel half; y==0 also copies the word emb.
// ---------------------------------------------------------------------------
struct H4 { __half2 a, b; };

__device__ __forceinline__ H4 h4add(H4 x, H4 y) {
    H4 r; r.a = __hadd2(x.a, y.a); r.b = __hadd2(x.b, y.b); return r;
}
__device__ __forceinline__ H4 h4max(H4 x, H4 y) {
    H4 r; r.a = __hmax2(x.a, y.a); r.b = __hmax2(x.b, y.b); return r;
}

extern "C" __global__ void __launch_bounds__(512, 2)
wordchar_main_kernel(const int* __restrict__ X,
                     const int* __restrict__ Xword,
                     const float* __restrict__ conv_b,
                     const float* __restrict__ wemb,
                     float* __restrict__ out) {
    extern __shared__ __align__(16) char smem_raw[];
    // table: [3][128 chars][OCHUNK halves] = 3*128*256B = 96 KB
    H4*   Ms  = reinterpret_cast<H4*>(smem_raw);             // 8B units, 32 per row
    uint4* Ms16 = reinterpret_cast<uint4*>(smem_raw);        // for staging

    const int half_id = blockIdx.y;
    const int o_base  = half_id * OCHUNK;

    // stage the fp16 table chunk: 3*128 rows x 256B (16 uint4 per row)
    {
        const uint4* Mg16 = reinterpret_cast<const uint4*>(g_Mh);
        const int n16 = 3 * 128 * 16;                        // 6144
        for (int i = threadIdx.x; i < n16; i += blockDim.x) {
            int row = i >> 4;          // (k*128 + c)
            int j   = i & 15;
            Ms16[i] = Mg16[row * 32 + half_id * 16 + j];
        }
    }
    __syncthreads();

    const int warp   = threadIdx.x >> 5;
    const int lane   = threadIdx.x & 31;
    const int gwarp  = blockIdx.x * 16 + warp;
    const int nwarps = gridDim.x * 16;

    const float4 b4 = *reinterpret_cast<const float4*>(conv_b + o_base + lane * 4);

    for (int w = gwarp; w < NW; w += nwarps) {
        const int4* xr = reinterpret_cast<const int4*>(X + w * LCH);
        int4 x0 = xr[0], x1 = xr[1], x2 = xr[2], x3 = xr[3];
        int xs[16];
        xs[0]=x0.x; xs[1]=x0.y; xs[2]=x0.z; xs[3]=x0.w;
        xs[4]=x1.x; xs[5]=x1.y; xs[6]=x1.z; xs[7]=x1.w;
        xs[8]=x2.x; xs[9]=x2.y; xs[10]=x2.z; xs[11]=x2.w;
        xs[12]=x3.x; xs[13]=x3.y; xs[14]=x3.z; xs[15]=x3.w;

        // sliding window: y[t] = M0[x[t-2]] + M1[x[t-1]] + M2[x[t]]
        H4 maxs, pp0, p0, p1;
#pragma unroll
        for (int t = 0; t < 16; ++t) {
            int c = xs[t];
            H4 m0 = Ms[(0 * 128 + c) * 32 + lane];
            H4 m1 = Ms[(1 * 128 + c) * 32 + lane];
            H4 m2 = Ms[(2 * 128 + c) * 32 + lane];
            H4 y = m2;
            if (t >= 1) y = h4add(y, p1);
            if (t >= 2) y = h4add(y, pp0);
            maxs = (t == 0) ? y : h4max(maxs, y);
            pp0 = p0;
            p0  = m0;
            p1  = m1;
        }
        maxs = h4max(maxs, h4add(p1, pp0));   // t = 16
        maxs = h4max(maxs, p0);               // t = 17

        // convert, add bias (fp32), relu, store
        float2 f0 = __half22float2(maxs.a);
        float2 f1 = __half22float2(maxs.b);
        float4 r;
        r.x = fmaxf(f0.x + b4.x, 0.f);
        r.y = fmaxf(f0.y + b4.y, 0.f);
        r.z = fmaxf(f1.x + b4.z, 0.f);
        r.w = fmaxf(f1.y + b4.w, 0.f);
        *reinterpret_cast<float4*>(out + (size_t)w * OUTW + o_base + lane * 4) = r;

        if (half_id == 0) {
            int wi = Xword[w];
            const float4* src = reinterpret_cast<const float4*>(wemb + (size_t)wi * DEMB);
            float4* dst = reinterpret_cast<float4*>(out + (size_t)w * OUTW + CO);
#pragma unroll
            for (int j = lane; j < DEMB / 4; j += 32)   // 75 float4
                dst[j] = src[j];
        }
    }
}

// ---------------------------------------------------------------------------
// Launch
// ---------------------------------------------------------------------------
extern "C" void kernel_launch(void* const* d_in, const int* in_sizes, int n_in,
                              void* d_out, int out_size) {
    const int*   X        = (const int*)  d_in[0];   // [16384,16]
    const int*   X_word   = (const int*)  d_in[1];   // [16384]
    const float* char_emb = (const float*)d_in[2];   // [128,64]
    const float* conv_w   = (const float*)d_in[3];   // [256,64,3]
    const float* conv_b   = (const float*)d_in[4];   // [256]
    const float* word_emb = (const float*)d_in[5];   // [50000,300]
    float*       out      = (float*)d_out;           // [16384,556]

    build_tables_kernel<<<128, 256>>>(char_emb, conv_w);

    const int smem = 3 * 128 * OCHUNK * (int)sizeof(__half);   // 98304
    cudaFuncSetAttribute(wordchar_main_kernel,
                         cudaFuncAttributeMaxDynamicSharedMemorySize, smem);
    dim3 grid(148, 2);
    wordchar_main_kernel<<<grid, 512, smem>>>(X, X_word, conv_b, word_emb, out);
}

// round 3
// speedup vs baseline: 1.3033x; 1.2618x over previous
#include <cuda_runtime.h>
#include <cuda_fp16.h>

// Problem constants
#define NW      16384   // words
#define LCH     16      // chars per word
#define CEMB    64      // char emb dim
#define CO      256     // conv out channels
#define DEMB    300     // word emb dim
#define OUTW    556     // 256 + 300
#define OCHUNK  128     // channels per block (blockIdx.y in {0,1})

// Precomputed conv tables (fp16): M[k][c][o] = sum_e char_emb[c,e]*conv_w[o,e,k]
__device__ __half g_Mh[3 * 128 * 256];

// ---------------------------------------------------------------------------
// Kernel 1: build tables. grid = 256 (o), block = 128 (c).
// conv_w reads are warp-UNIFORM (broadcast) -> 1 wavefront per load.
// ---------------------------------------------------------------------------
__global__ void build_tables_kernel(const float* __restrict__ ce_w,
                                    const float* __restrict__ conv_w) {
    __shared__ float se[64 * 128];   // se[e*128 + c]
    const int o = blockIdx.x;
    const int c = threadIdx.x;

    for (int i = threadIdx.x; i < 128 * 64; i += 128) {
        int cc = i >> 6;
        int e  = i & 63;
        se[e * 128 + cc] = ce_w[i];   // coalesced read, conflict-free write
    }
    __syncthreads();

    const float* wp = conv_w + o * (CEMB * 3);   // uniform across the block
    float a0 = 0.f, a1 = 0.f, a2 = 0.f;
#pragma unroll
    for (int e = 0; e < CEMB; ++e) {
        float w0 = wp[e * 3 + 0];    // broadcast
        float w1 = wp[e * 3 + 1];
        float w2 = wp[e * 3 + 2];
        float s  = se[e * 128 + c];
        a0 = fmaf(s, w0, a0);
        a1 = fmaf(s, w1, a1);
        a2 = fmaf(s, w2, a2);
    }
    g_Mh[(0 * 128 + c) * 256 + o] = __float2half_rn(a0);
    g_Mh[(1 * 128 + c) * 256 + o] = __float2half_rn(a1);
    g_Mh[(2 * 128 + c) * 256 + o] = __float2half_rn(a2);
}

// ---------------------------------------------------------------------------
// Kernel 2: main. grid = (148, 2), block = 512, 96 KB dyn smem, 2 CTAs/SM.
// Each warp handles TWO words: lanes 0-15 word A, lanes 16-31 word B.
// Each lane covers 8 channels as one H8 (LDS.128, 16B).
// ---------------------------------------------------------------------------
struct H8 { __half2 a, b, c, d; };

__device__ __forceinline__ H8 h8add(H8 x, H8 y) {
    H8 r; r.a = __hadd2(x.a, y.a); r.b = __hadd2(x.b, y.b);
    r.c = __hadd2(x.c, y.c); r.d = __hadd2(x.d, y.d); return r;
}
__device__ __forceinline__ H8 h8max(H8 x, H8 y) {
    H8 r; r.a = __hmax2(x.a, y.a); r.b = __hmax2(x.b, y.b);
    r.c = __hmax2(x.c, y.c); r.d = __hmax2(x.d, y.d); return r;
}

extern "C" __global__ void __launch_bounds__(512, 2)
wordchar_main_kernel(const int* __restrict__ X,
                     const int* __restrict__ Xword,
                     const float* __restrict__ conv_b,
                     const float* __restrict__ wemb,
                     float* __restrict__ out) {
    extern __shared__ __align__(16) char smem_raw[];
    H8*    Ms   = reinterpret_cast<H8*>(smem_raw);     // [(k*128+c)*16 + sl]
    uint4* Ms16 = reinterpret_cast<uint4*>(smem_raw);

    const int half_id = blockIdx.y;
    const int o_base  = half_id * OCHUNK;

    // stage the fp16 table chunk: 3*128 rows x 256B (16 uint4 per row)
    {
        const uint4* Mg16 = reinterpret_cast<const uint4*>(g_Mh);
        const int n16 = 3 * 128 * 16;                  // 6144
        for (int i = threadIdx.x; i < n16; i += blockDim.x) {
            int row = i >> 4;                          // (k*128 + c)
            int j   = i & 15;
            Ms16[i] = Mg16[row * 32 + half_id * 16 + j];
        }
    }
    __syncthreads();

    const int warp = threadIdx.x >> 5;
    const int lane = threadIdx.x & 31;
    const int sub  = lane >> 4;        // which word of the pair
    const int sl   = lane & 15;        // 16 lanes cover 128 channels (8 each)

    const int gw      = blockIdx.x * 16 + warp;
    const int nwarps  = gridDim.x * 16;

    // bias for this lane's 8 channels
    const float4* bp = reinterpret_cast<const float4*>(conv_b + o_base + sl * 8);
    const float4 bA = bp[0], bB = bp[1];

    const H8 zero = { __float2half2_rn(0.f), __float2half2_rn(0.f),
                      __float2half2_rn(0.f), __float2half2_rn(0.f) };

    for (int p = gw; p < NW / 2; p += nwarps) {
        const int w = 2 * p + sub;

        const int4* xr = reinterpret_cast<const int4*>(X + w * LCH);
        int4 x0 = xr[0], x1 = xr[1], x2 = xr[2], x3 = xr[3];
        int xs[16];
        xs[0]=x0.x; xs[1]=x0.y; xs[2]=x0.z; xs[3]=x0.w;
        xs[4]=x1.x; xs[5]=x1.y; xs[6]=x1.z; xs[7]=x1.w;
        xs[8]=x2.x; xs[9]=x2.y; xs[10]=x2.z; xs[11]=x2.w;
        xs[12]=x3.x; xs[13]=x3.y; xs[14]=x3.z; xs[15]=x3.w;

        // carry-chain sliding window:
        //   y[t] = M2[x_t] + c1,  c1' = M1[x_t] + c0,  c0' = M0[x_t]
        H8 maxs, c0 = zero, c1 = zero;
#pragma unroll
        for (int t = 0; t < 16; ++t) {
            int cc = xs[t];
            H8 m0 = Ms[(0 * 128 + cc) * 16 + sl];
            H8 m1 = Ms[(1 * 128 + cc) * 16 + sl];
            H8 m2 = Ms[(2 * 128 + cc) * 16 + sl];
            H8 y  = h8add(m2, c1);
            maxs  = (t == 0) ? y : h8max(maxs, y);
            c1 = h8add(m1, c0);
            c0 = m0;
        }
        maxs = h8max(maxs, c1);   // t = 16
        maxs = h8max(maxs, c0);   // t = 17

        // fp32 bias + relu + store (8 floats = 2x float4)
        float2 fa = __half22float2(maxs.a);
        float2 fb = __half22float2(maxs.b);
        float2 fc = __half22float2(maxs.c);
        float2 fd = __half22float2(maxs.d);
        float4 r0, r1;
        r0.x = fmaxf(fa.x + bA.x, 0.f);
        r0.y = fmaxf(fa.y + bA.y, 0.f);
        r0.z = fmaxf(fb.x + bA.z, 0.f);
        r0.w = fmaxf(fb.y + bA.w, 0.f);
        r1.x = fmaxf(fc.x + bB.x, 0.f);
        r1.y = fmaxf(fc.y + bB.y, 0.f);
        r1.z = fmaxf(fd.x + bB.z, 0.f);
        r1.w = fmaxf(fd.y + bB.w, 0.f);
        float4* op = reinterpret_cast<float4*>(out + (size_t)w * OUTW + o_base + sl * 8);
        op[0] = r0;
        op[1] = r1;

        // word embedding copy: each half-warp copies its own word's 300 floats
        if (half_id == 0) {
            int wi = Xword[w];
            const float4* src = reinterpret_cast<const float4*>(wemb + (size_t)wi * DEMB);
            float4* dst = reinterpret_cast<float4*>(out + (size_t)w * OUTW + CO);
#pragma unroll
            for (int j = sl; j < DEMB / 4; j += 16)   // 75 float4 per word
                dst[j] = src[j];
        }
    }
}

// ---------------------------------------------------------------------------
// Launch
// ---------------------------------------------------------------------------
extern "C" void kernel_launch(void* const* d_in, const int* in_sizes, int n_in,
                              void* d_out, int out_size) {
    const int*   X        = (const int*)  d_in[0];   // [16384,16]
    const int*   X_word   = (const int*)  d_in[1];   // [16384]
    const float* char_emb = (const float*)d_in[2];   // [128,64]
    const float* conv_w   = (const float*)d_in[3];   // [256,64,3]
    const float* conv_b   = (const float*)d_in[4];   // [256]
    const float* word_emb = (const float*)d_in[5];   // [50000,300]
    float*       out      = (float*)d_out;           // [16384,556]

    build_tables_kernel<<<256, 128>>>(char_emb, conv_w);

    const int smem = 3 * 128 * OCHUNK * (int)sizeof(__half);   // 98304
    cudaFuncSetAttribute(wordchar_main_kernel,
                         cudaFuncAttributeMaxDynamicSharedMemorySize, smem);
    dim3 grid(148, 2);
    wordchar_main_kernel<<<grid, 512, smem>>>(X, X_word, conv_b, word_emb, out);
}

// round 4
// speedup vs baseline: 1.3736x; 1.0540x over previous
#include <cuda_runtime.h>
#include <cuda_fp16.h>

// Problem constants
#define NW      16384   // words
#define LCH     16      // chars per word
#define CEMB    64      // char emb dim
#define CO      256     // conv out channels
#define DEMB    300     // word emb dim
#define OUTW    556     // 256 + 300
#define OCHUNK  128     // channels per block (blockIdx.y in {0,1})

// Precomputed conv tables (fp16): M[k][c][o] = sum_e char_emb[c,e]*conv_w[o,e,k]
__device__ __half g_Mh[3 * 128 * 256];

// ---------------------------------------------------------------------------
// Kernel 1: build tables. grid = 256 (o), block = 128 (c).
// conv_w reads are warp-UNIFORM (broadcast) -> 1 wavefront per load.
// ---------------------------------------------------------------------------
__global__ void build_tables_kernel(const float* __restrict__ ce_w,
                                    const float* __restrict__ conv_w) {
    __shared__ float se[64 * 128];   // se[e*128 + c]
    const int o = blockIdx.x;
    const int c = threadIdx.x;

    for (int i = threadIdx.x; i < 128 * 64; i += 128) {
        int cc = i >> 6;
        int e  = i & 63;
        se[e * 128 + cc] = ce_w[i];   // coalesced read, conflict-free write
    }
    __syncthreads();

    const float* wp = conv_w + o * (CEMB * 3);   // uniform across the block
    float a0 = 0.f, a1 = 0.f, a2 = 0.f;
#pragma unroll
    for (int e = 0; e < CEMB; ++e) {
        float w0 = wp[e * 3 + 0];    // broadcast
        float w1 = wp[e * 3 + 1];
        float w2 = wp[e * 3 + 2];
        float s  = se[e * 128 + c];
        a0 = fmaf(s, w0, a0);
        a1 = fmaf(s, w1, a1);
        a2 = fmaf(s, w2, a2);
    }
    g_Mh[(0 * 128 + c) * 256 + o] = __float2half_rn(a0);
    g_Mh[(1 * 128 + c) * 256 + o] = __float2half_rn(a1);
    g_Mh[(2 * 128 + c) * 256 + o] = __float2half_rn(a2);
}

// ---------------------------------------------------------------------------
// Kernel 2: main. grid = (148, 2), block = 512, 96 KB dyn smem, 2 CTAs/SM.
// Round-2 proven shape: warp = one word, lane = 4 channels (H4, LDS.64).
// Word-embedding copy split BETWEEN the two halves (balanced DRAM work).
// ---------------------------------------------------------------------------
struct H4 { __half2 a, b; };

__device__ __forceinline__ H4 h4add(H4 x, H4 y) {
    H4 r; r.a = __hadd2(x.a, y.a); r.b = __hadd2(x.b, y.b); return r;
}
__device__ __forceinline__ H4 h4max(H4 x, H4 y) {
    H4 r; r.a = __hmax2(x.a, y.a); r.b = __hmax2(x.b, y.b); return r;
}

extern "C" __global__ void __launch_bounds__(512, 2)
wordchar_main_kernel(const int* __restrict__ X,
                     const int* __restrict__ Xword,
                     const float* __restrict__ conv_b,
                     const float* __restrict__ wemb,
                     float* __restrict__ out) {
    extern __shared__ __align__(16) char smem_raw[];
    H4*    Ms   = reinterpret_cast<H4*>(smem_raw);     // [(k*128+c)*32 + lane]
    uint4* Ms16 = reinterpret_cast<uint4*>(smem_raw);

    const int half_id = blockIdx.y;
    const int o_base  = half_id * OCHUNK;

    // stage the fp16 table chunk: 3*128 rows x 256B (16 uint4 per row)
    {
        const uint4* Mg16 = reinterpret_cast<const uint4*>(g_Mh);
        const int n16 = 3 * 128 * 16;                  // 6144
        for (int i = threadIdx.x; i < n16; i += blockDim.x) {
            int row = i >> 4;                          // (k*128 + c)
            int j   = i & 15;
            Ms16[i] = Mg16[row * 32 + half_id * 16 + j];
        }
    }
    __syncthreads();

    const int warp   = threadIdx.x >> 5;
    const int lane   = threadIdx.x & 31;
    const int gwarp  = blockIdx.x * 16 + warp;
    const int nwarps = gridDim.x * 16;

    const float4 b4 = *reinterpret_cast<const float4*>(conv_b + o_base + lane * 4);

    // this half's slice of the 75-float4 word-embedding copy
    const int j_lo = (half_id == 0) ? 0  : 38;
    const int j_hi = (half_id == 0) ? 38 : 75;

    const H4 zero = { __float2half2_rn(0.f), __float2half2_rn(0.f) };

    for (int w = gwarp; w < NW; w += nwarps) {
        const int4* xr = reinterpret_cast<const int4*>(X + w * LCH);
        int4 x0 = xr[0], x1 = xr[1], x2 = xr[2], x3 = xr[3];
        int xs[16];
        xs[0]=x0.x; xs[1]=x0.y; xs[2]=x0.z; xs[3]=x0.w;
        xs[4]=x1.x; xs[5]=x1.y; xs[6]=x1.z; xs[7]=x1.w;
        xs[8]=x2.x; xs[9]=x2.y; xs[10]=x2.z; xs[11]=x2.w;
        xs[12]=x3.x; xs[13]=x3.y; xs[14]=x3.z; xs[15]=x3.w;

        // kick off the word-embedding gather early (independent of conv)
        const int wi = Xword[w];
        const float4* src = reinterpret_cast<const float4*>(wemb + (size_t)wi * DEMB);
        float4* dst = reinterpret_cast<float4*>(out + (size_t)w * OUTW + CO);
        float4 e0, e1;
        int j0 = j_lo + lane;            // first 32 of this half's slice
        int j1 = j_lo + 32 + lane;       // remaining few
        bool p0 = (j0 < j_hi);
        bool p1 = (j1 < j_hi);
        if (p0) e0 = src[j0];
        if (p1) e1 = src[j1];

        // carry-chain sliding window:
        //   y[t] = M2[x_t] + c1,  c1' = M1[x_t] + c0,  c0' = M0[x_t]
        H4 maxs, c0 = zero, c1 = zero;
#pragma unroll
        for (int t = 0; t < 16; ++t) {
            int cc = xs[t];
            H4 m0 = Ms[(0 * 128 + cc) * 32 + lane];
            H4 m1 = Ms[(1 * 128 + cc) * 32 + lane];
            H4 m2 = Ms[(2 * 128 + cc) * 32 + lane];
            H4 y  = h4add(m2, c1);
            maxs  = (t == 0) ? y : h4max(maxs, y);
            c1 = h4add(m1, c0);
            c0 = m0;
        }
        maxs = h4max(maxs, c1);   // t = 16
        maxs = h4max(maxs, c0);   // t = 17

        // fp32 bias + relu + store
        float2 f0 = __half22float2(maxs.a);
        float2 f1 = __half22float2(maxs.b);
        float4 r;
        r.x = fmaxf(f0.x + b4.x, 0.f);
        r.y = fmaxf(f0.y + b4.y, 0.f);
        r.z = fmaxf(f1.x + b4.z, 0.f);
        r.w = fmaxf(f1.y + b4.w, 0.f);
        *reinterpret_cast<float4*>(out + (size_t)w * OUTW + o_base + lane * 4) = r;

        // complete this half's share of the embedding copy
        if (p0) dst[j0] = e0;
        if (p1) dst[j1] = e1;
    }
}

// ---------------------------------------------------------------------------
// Launch
// ---------------------------------------------------------------------------
extern "C" void kernel_launch(void* const* d_in, const int* in_sizes, int n_in,
                              void* d_out, int out_size) {
    const int*   X        = (const int*)  d_in[0];   // [16384,16]
    const int*   X_word   = (const int*)  d_in[1];   // [16384]
    const float* char_emb = (const float*)d_in[2];   // [128,64]
    const float* conv_w   = (const float*)d_in[3];   // [256,64,3]
    const float* conv_b   = (const float*)d_in[4];   // [256]
    const float* word_emb = (const float*)d_in[5];   // [50000,300]
    float*       out      = (float*)d_out;           // [16384,556]

    build_tables_kernel<<<256, 128>>>(char_emb, conv_w);

    const int smem = 3 * 128 * OCHUNK * (int)sizeof(__half);   // 98304
    cudaFuncSetAttribute(wordchar_main_kernel,
                         cudaFuncAttributeMaxDynamicSharedMemorySize, smem);
    dim3 grid(148, 2);
    wordchar_main_kernel<<<grid, 512, smem>>>(X, X_word, conv_b, word_emb, out);
}